// round 13
// baseline (speedup 1.0000x reference)
#include <cuda_runtime.h>
#include <cstdint>

#define DDIM     64
#define MROWS    128
#define BK       64
#define KCODES   1024
#define NCHUNKS  (KCODES / BK)      /* 16 */
#define HW       4096
#define NTOT     (32 * 64 * 64)     /* 131072 rows */
#define NTHREADS 256
#define EPS      1e-2f              /* rescue margin; approx error bound ~1e-4 */

/* ---- dynamic smem layout (bytes): 104 KB -> 2 CTAs/SM ---- */
#define SM_EK2   0                  /* 4 KB  */
#define SM_IDX   4096               /* 512 B */
#define SM_WS    4608               /* 32 B  */
#define SM_A4    8192               /* 64 KB  A fragments */
#define SM_B4    73728              /* 32 KB  B fragments */
#define SMEM_TOTAL 106496

__device__ __align__(16) float g_ek2[KCODES];
__device__ double g_loss;

/* ================= helpers ================= */
__device__ __forceinline__ void mma_tf32(float& c0, float& c1, float& c2, float& c3,
                                         uint32_t a0, uint32_t a1, uint32_t a2, uint32_t a3,
                                         uint32_t b0, uint32_t b1) {
    asm volatile(
        "mma.sync.aligned.m16n8k8.row.col.f32.tf32.tf32.f32 "
        "{%0,%1,%2,%3},{%4,%5,%6,%7},{%8,%9},{%0,%1,%2,%3};"
        : "+f"(c0), "+f"(c1), "+f"(c2), "+f"(c3)
        : "r"(a0), "r"(a1), "r"(a2), "r"(a3), "r"(b0), "r"(b1));
}

/* split fp32 into two valid tf32 values (hi + lo ~ v, both 13 low bits zero) */
__device__ __forceinline__ void split_tf32(float v, uint32_t& hi, uint32_t& lo) {
    uint32_t h = __float_as_uint(v) & 0xFFFFE000u;
    float l = v - __uint_as_float(h);
    hi = h;
    lo = __float_as_uint(l) & 0xFFFFE000u;
}

/* exact fp32 distance from gmem z (sequential accumulation, matches scalar kernel) */
__device__ __forceinline__ float exact_dist(const float* zb, const float* emb,
                                            const float* ek2s, int row, int idx) {
    const float* er = emb + (size_t)idx * DDIM;
    float dot = 0.f;
#pragma unroll
    for (int d = 0; d < DDIM; d++)
        dot = fmaf(__ldg(zb + (size_t)d * HW + row), __ldg(er + d), dot);
    return fmaf(dot, -2.f, ek2s[idx]);
}

/* ================= small kernels ================= */
__global__ void zero_loss_kernel() { g_loss = 0.0; }

__global__ void ek2_kernel(const float* __restrict__ emb) {
    int k = blockIdx.x * blockDim.x + threadIdx.x;
    if (k >= KCODES) return;
    const float4* e4 = (const float4*)(emb + (size_t)k * DDIM);
    float s = 0.f;
#pragma unroll
    for (int i = 0; i < DDIM / 4; i++) {
        float4 v = e4[i];
        s += v.x * v.x + v.y * v.y + v.z * v.z + v.w * v.w;
    }
    g_ek2[k] = s;
}

__global__ void finalize_kernel(float* out, int loss_idx) {
    out[loss_idx] = (float)(g_loss * (1.25 / 8388608.0));
}

/* ================= main kernel ================= */
__global__ void __launch_bounds__(NTHREADS, 2)
vq_kernel(const float* __restrict__ z, const float* __restrict__ emb,
          float* __restrict__ out) {
    extern __shared__ char smem[];
    float* ek2s  = (float*)(smem + SM_EK2);
    int*   idx_s = (int*)(smem + SM_IDX);
    float* wsum  = (float*)(smem + SM_WS);
    char*  A4    = smem + SM_A4;
    char*  B4    = smem + SM_B4;

    const int tid  = threadIdx.x;
    const int lane = tid & 31;
    const int w    = tid >> 5;        /* warp id: owns rows w*16 .. w*16+15 */
    const int g    = lane >> 2;       /* group id 0-7 */
    const int t    = lane & 3;        /* thread-in-group 0-3 */

    const int nbase = blockIdx.x * MROWS;
    const int b   = nbase >> 12;
    const int hw0 = nbase & (HW - 1);
    const float* zb = z + (size_t)b * DDIM * HW + hw0;

    /* ---- ek2 to smem ---- */
#pragma unroll
    for (int it = 0; it < 4; it++)
        ek2s[it * NTHREADS + tid] = g_ek2[it * NTHREADS + tid];

    /* ---- build A4 straight from gmem z:
       per (row, kg): float4 j = (hi[8kg+j], hi[8kg+j+4], lo[..j], lo[..j+4]) ---- */
#pragma unroll
    for (int it = 0; it < 4; it++) {
        int p = it * NTHREADS + tid;             /* 1024 (row,kg) pairs */
        int kg = p & 7, row = p >> 3;
        uint32_t hi[8], lo[8];
#pragma unroll
        for (int q = 0; q < 8; q++)
            split_tf32(__ldg(zb + (size_t)(kg * 8 + q) * HW + row), hi[q], lo[q]);
        char* dst = A4 + (row >> 4) * 8192 + kg * 1024 + (row & 15) * 64;
#pragma unroll
        for (int j = 0; j < 4; j++)
            *(uint4*)(dst + j * 16) = make_uint4(hi[j], hi[j + 4], lo[j], lo[j + 4]);
    }

    /* per-lane top-2 for each of the 2 row-slots */
    float va0 = 3.4e38f, vb0 = 3.4e38f, va1 = 3.4e38f, vb1 = 3.4e38f;
    int   ia0 = 0, ib0 = 0, ia1 = 0, ib1 = 0;

    /* B chunk staging: per thread 2 (kg,n) pairs, gmem-coalesced, one reg buffer */
    float4 pf[4];

    auto prefetch = [&](int k0) {
#pragma unroll
        for (int it = 0; it < 2; it++) {
            int p = it * NTHREADS + tid;
            int kg = p & 7, n = p >> 3;
            const float4* src = (const float4*)(emb + (size_t)(k0 + n) * DDIM + kg * 8);
            pf[it * 2]     = __ldg(src);
            pf[it * 2 + 1] = __ldg(src + 1);
        }
    };
    auto sts_b = [&]() {
#pragma unroll
        for (int it = 0; it < 2; it++) {
            int p = it * NTHREADS + tid;
            int kg = p & 7, n = p >> 3;
            float v[8] = {pf[it*2].x, pf[it*2].y, pf[it*2].z, pf[it*2].w,
                          pf[it*2+1].x, pf[it*2+1].y, pf[it*2+1].z, pf[it*2+1].w};
            uint32_t hi[8], lo[8];
#pragma unroll
            for (int q = 0; q < 8; q++) split_tf32(v[q], hi[q], lo[q]);
            char* dst = B4 + kg * 4096 + (n >> 3) * 512 + (n & 7) * 64;
#pragma unroll
            for (int j = 0; j < 4; j++)
                *(uint4*)(dst + j * 16) = make_uint4(hi[j], hi[j + 4], lo[j], lo[j + 4]);
        }
    };

    prefetch(0);
    const char* aw = A4 + w * 8192;

    for (int c = 0; c < NCHUNKS; c++) {
        const int k0 = c * BK;
        __syncthreads();                 /* B4 free (prev chunk consumed); A4 ready on c==0 */
        sts_b();
        if (c + 1 < NCHUNKS) prefetch(k0 + BK);   /* LDGs complete under mma below */
        __syncthreads();                 /* B4 holds chunk c */

        float C[8][4];
#pragma unroll
        for (int nt = 0; nt < 8; nt++)
#pragma unroll
            for (int q = 0; q < 4; q++) C[nt][q] = 0.f;

#pragma unroll
        for (int kg = 0; kg < 8; kg++) {
            uint4 f1 = *(const uint4*)(aw + kg * 1024 + g * 64 + t * 16);
            uint4 f2 = *(const uint4*)(aw + kg * 1024 + (g + 8) * 64 + t * 16);
            uint32_t ah0 = f1.x, ah1 = f2.x, ah2 = f1.y, ah3 = f2.y;
            uint32_t al0 = f1.z, al1 = f2.z, al2 = f1.w, al3 = f2.w;
            const char* bkg = B4 + kg * 4096 + g * 64 + t * 16;

            /* pass 0: hi*hi */
#pragma unroll
            for (int nt = 0; nt < 8; nt++) {
                uint2 bh = *(const uint2*)(bkg + nt * 512);
                mma_tf32(C[nt][0], C[nt][1], C[nt][2], C[nt][3],
                         ah0, ah1, ah2, ah3, bh.x, bh.y);
            }
            /* pass 1: hi*lo */
#pragma unroll
            for (int nt = 0; nt < 8; nt++) {
                uint2 bl = *(const uint2*)(bkg + nt * 512 + 8);
                mma_tf32(C[nt][0], C[nt][1], C[nt][2], C[nt][3],
                         ah0, ah1, ah2, ah3, bl.x, bl.y);
            }
            /* pass 2: lo*hi */
#pragma unroll
            for (int nt = 0; nt < 8; nt++) {
                uint2 bh = *(const uint2*)(bkg + nt * 512);
                mma_tf32(C[nt][0], C[nt][1], C[nt][2], C[nt][3],
                         al0, al1, al2, al3, bh.x, bh.y);
            }
        }

        /* top-2 update: rows (w*16+g, w*16+8+g), cols k0 + nt*8 + 2t(+1) */
#pragma unroll
        for (int nt = 0; nt < 8; nt++) {
            int c0i = k0 + nt * 8 + 2 * t;
            float2 e2 = *(const float2*)(ek2s + c0i);
            float s0 = fmaf(C[nt][0], -2.f, e2.x);
            float s1 = fmaf(C[nt][1], -2.f, e2.y);
            float s2 = fmaf(C[nt][2], -2.f, e2.x);
            float s3 = fmaf(C[nt][3], -2.f, e2.y);
            if (s0 < va0)      { vb0 = va0; ib0 = ia0; va0 = s0; ia0 = c0i; }
            else if (s0 < vb0) { vb0 = s0; ib0 = c0i; }
            if (s1 < va0)      { vb0 = va0; ib0 = ia0; va0 = s1; ia0 = c0i + 1; }
            else if (s1 < vb0) { vb0 = s1; ib0 = c0i + 1; }
            if (s2 < va1)      { vb1 = va1; ib1 = ia1; va1 = s2; ia1 = c0i; }
            else if (s2 < vb1) { vb1 = s2; ib1 = c0i; }
            if (s3 < va1)      { vb1 = va1; ib1 = ia1; va1 = s3; ia1 = c0i + 1; }
            else if (s3 < vb1) { vb1 = s3; ib1 = c0i + 1; }
        }
    }

    /* ---- cross-lane top-2 merge over t (first-occurrence tie rule on best) ---- */
#pragma unroll
    for (int o = 1; o <= 2; o <<= 1) {
        {
            float pa = __shfl_xor_sync(0xffffffffu, va0, o);
            float pb = __shfl_xor_sync(0xffffffffu, vb0, o);
            int pia = __shfl_xor_sync(0xffffffffu, ia0, o);
            int pib = __shfl_xor_sync(0xffffffffu, ib0, o);
            bool pwin = (pa < va0) || (pa == va0 && pia < ia0);
            if (pwin) {
                bool s2 = (pb < va0) || (pb == va0 && pib < ia0);
                vb0 = s2 ? pb : va0; ib0 = s2 ? pib : ia0;
                va0 = pa; ia0 = pia;
            } else {
                bool s2 = (vb0 < pa) || (vb0 == pa && ib0 < pia);
                vb0 = s2 ? vb0 : pa; ib0 = s2 ? ib0 : pia;
            }
        }
        {
            float pa = __shfl_xor_sync(0xffffffffu, va1, o);
            float pb = __shfl_xor_sync(0xffffffffu, vb1, o);
            int pia = __shfl_xor_sync(0xffffffffu, ia1, o);
            int pib = __shfl_xor_sync(0xffffffffu, ib1, o);
            bool pwin = (pa < va1) || (pa == va1 && pia < ia1);
            if (pwin) {
                bool s2 = (pb < va1) || (pb == va1 && pib < ia1);
                vb1 = s2 ? pb : va1; ib1 = s2 ? pib : ia1;
                va1 = pa; ia1 = pia;
            } else {
                bool s2 = (vb1 < pa) || (vb1 == pa && ib1 < pia);
                vb1 = s2 ? vb1 : pa; ib1 = s2 ? ib1 : pia;
            }
        }
    }

    if (t == 0) {
        int row0 = w * 16 + g, row1 = w * 16 + 8 + g;
        int bi0 = ia0;
        if (vb0 - va0 < EPS) {   /* near-tie: exact fp32 rescue */
            float da = exact_dist(zb, emb, ek2s, row0, ia0);
            float db = exact_dist(zb, emb, ek2s, row0, ib0);
            if (db < da || (db == da && ib0 < ia0)) bi0 = ib0;
        }
        int bi1 = ia1;
        if (vb1 - va1 < EPS) {
            float da = exact_dist(zb, emb, ek2s, row1, ia1);
            float db = exact_dist(zb, emb, ek2s, row1, ib1);
            if (db < da || (db == da && ib1 < ia1)) bi1 = ib1;
        }
        idx_s[row0] = bi0;
        idx_s[row1] = bi1;
    }
    __syncthreads();

    /* ---- epilogue: gather codebook rows, transposed coalesced store, loss
       (z re-read coalesced from gmem) ---- */
    float* outb = out + (size_t)b * DDIM * HW + hw0;
    float lsum = 0.f;
#pragma unroll
    for (int it = 0; it < 32; it++) {
        int e = it * NTHREADS + tid;       /* 8192 elements */
        int d = e >> 7, i = e & 127;
        float q = __ldg(emb + (size_t)idx_s[i] * DDIM + d);
        outb[(size_t)d * HW + i] = q;
        float diff = q - __ldg(zb + (size_t)d * HW + i);
        lsum += diff * diff;
    }
#pragma unroll
    for (int o = 16; o > 0; o >>= 1)
        lsum += __shfl_xor_sync(0xffffffffu, lsum, o);
    if (lane == 0) wsum[w] = lsum;
    __syncthreads();
    if (tid == 0) {
        float tot = 0.f;
#pragma unroll
        for (int j = 0; j < 8; j++) tot += wsum[j];
        atomicAdd(&g_loss, (double)tot);
    }
}

/* ================= launch ================= */
extern "C" void kernel_launch(void* const* d_in, const int* in_sizes, int n_in,
                              void* d_out, int out_size) {
    const float* z   = (const float*)d_in[0];
    const float* emb = (const float*)d_in[1];
    float* out = (float*)d_out;

    static int attr_set = 0;
    if (!attr_set) {
        cudaFuncSetAttribute(vq_kernel, cudaFuncAttributeMaxDynamicSharedMemorySize,
                             SMEM_TOTAL);
        attr_set = 1;
    }

    zero_loss_kernel<<<1, 1>>>();
    ek2_kernel<<<KCODES / 128, 128>>>(emb);
    vq_kernel<<<NTOT / MROWS, NTHREADS, SMEM_TOTAL>>>(z, emb, out);
    finalize_kernel<<<1, 1>>>(out, out_size - 1);
}

// round 16
// speedup vs baseline: 1.8955x; 1.8955x over previous
#include <cuda_runtime.h>
#include <cuda_bf16.h>
#include <cstdint>

#define DDIM     64
#define MROWS    128
#define BK       64
#define KCODES   1024
#define NCHUNKS  (KCODES / BK)      /* 16 */
#define HW       4096
#define NTOT     (32 * 64 * 64)     /* 131072 rows */
#define NTHREADS 256
#define EPS      1e-2f              /* rescue margin; bf16-split error ~4e-4 */

/* ---- dynamic smem layout (bytes): 90112 total ---- */
#define SM_EK2   0                  /* 4 KB  */
#define SM_IDX   4096               /* 512 B */
#define SM_WS    4608               /* 32 B  */
#define SM_ZS    8192               /* 32 KB  zs[d][128] */
#define SM_A4    40960              /* 32 KB  A bf16 fragments */
#define SM_B4    73728              /* 16 KB  B bf16 fragments */
#define SMEM_TOTAL 90112

__device__ __align__(16) float g_ek2[KCODES];
__device__ double g_loss;

/* ================= helpers ================= */
__device__ __forceinline__ void mma_bf16(float& c0, float& c1, float& c2, float& c3,
                                         uint32_t a0, uint32_t a1, uint32_t a2, uint32_t a3,
                                         uint32_t b0, uint32_t b1) {
    asm volatile(
        "mma.sync.aligned.m16n8k16.row.col.f32.bf16.bf16.f32 "
        "{%0,%1,%2,%3},{%4,%5,%6,%7},{%8,%9},{%0,%1,%2,%3};"
        : "+f"(c0), "+f"(c1), "+f"(c2), "+f"(c3)
        : "r"(a0), "r"(a1), "r"(a2), "r"(a3), "r"(b0), "r"(b1));
}

/* split two floats into packed bf16x2 (hi) + packed bf16x2 (lo residual) */
__device__ __forceinline__ void split2(float x, float y, uint32_t& hp, uint32_t& lp) {
    __nv_bfloat162 h = __floats2bfloat162_rn(x, y);
    float rx = x - __bfloat162float(__low2bfloat16(h));
    float ry = y - __bfloat162float(__high2bfloat16(h));
    __nv_bfloat162 l = __floats2bfloat162_rn(rx, ry);
    hp = *(uint32_t*)&h;
    lp = *(uint32_t*)&l;
}

/* exact fp32 distance (sequential accumulation, matches passing scalar kernel) */
__device__ __forceinline__ float exact_dist(const float* zs, const float* emb,
                                            const float* ek2s, int row, int idx) {
    const float* er = emb + (size_t)idx * DDIM;
    float dot = 0.f;
#pragma unroll
    for (int d = 0; d < DDIM; d++)
        dot = fmaf(zs[d * MROWS + row], __ldg(er + d), dot);
    return fmaf(dot, -2.f, ek2s[idx]);
}

/* ================= small kernels ================= */
__global__ void zero_loss_kernel() { g_loss = 0.0; }

__global__ void ek2_kernel(const float* __restrict__ emb) {
    int k = blockIdx.x * blockDim.x + threadIdx.x;
    if (k >= KCODES) return;
    const float4* e4 = (const float4*)(emb + (size_t)k * DDIM);
    float s = 0.f;
#pragma unroll
    for (int i = 0; i < DDIM / 4; i++) {
        float4 v = e4[i];
        s += v.x * v.x + v.y * v.y + v.z * v.z + v.w * v.w;
    }
    g_ek2[k] = s;
}

__global__ void finalize_kernel(float* out, int loss_idx) {
    out[loss_idx] = (float)(g_loss * (1.25 / 8388608.0));
}

/* ================= main kernel ================= */
__global__ void __launch_bounds__(NTHREADS)
vq_kernel(const float* __restrict__ z, const float* __restrict__ emb,
          float* __restrict__ out) {
    extern __shared__ char smem[];
    float* ek2s  = (float*)(smem + SM_EK2);
    int*   idx_s = (int*)(smem + SM_IDX);
    float* wsum  = (float*)(smem + SM_WS);
    float* zs    = (float*)(smem + SM_ZS);     /* [64][128] */
    char*  A4    = smem + SM_A4;
    char*  B4    = smem + SM_B4;

    const int tid  = threadIdx.x;
    const int lane = tid & 31;
    const int w    = tid >> 5;        /* warp id: owns rows w*16 .. w*16+15 */
    const int g    = lane >> 2;       /* group id 0-7 */
    const int t    = lane & 3;        /* thread-in-group 0-3 */

    const int nbase = blockIdx.x * MROWS;
    const int b   = nbase >> 12;
    const int hw0 = nbase & (HW - 1);

    /* ---- ek2 to smem ---- */
#pragma unroll
    for (int it = 0; it < 4; it++)
        ek2s[it * NTHREADS + tid] = g_ek2[it * NTHREADS + tid];

    /* ---- z -> zs [d][row] (coalesced) ---- */
    const float* zb = z + (size_t)b * DDIM * HW + hw0;
#pragma unroll
    for (int it = 0; it < 8; it++) {
        int e4 = it * NTHREADS + tid;            /* 2048 float4 */
        int d = e4 >> 5, r4 = e4 & 31;
        *(float4*)(zs + d * MROWS + r4 * 4) = *(const float4*)(zb + (size_t)d * HW + r4 * 4);
    }
    __syncthreads();

    /* ---- build A4: per (row, kg16) entry of 64 B:
       uint4 j = (hi_pair[j], hi_pair[j+4], lo_pair[j], lo_pair[j+4]), j=0..3,
       pair j covers k = kg16*16 + 2j, 2j+1 ---- */
#pragma unroll
    for (int it = 0; it < 2; it++) {
        int p = it * NTHREADS + tid;             /* 512 (row,kg16) entries */
        int kg = p & 3, row = p >> 2;
        uint32_t hp[8], lp[8];
#pragma unroll
        for (int j = 0; j < 8; j++)
            split2(zs[(kg * 16 + 2 * j) * MROWS + row],
                   zs[(kg * 16 + 2 * j + 1) * MROWS + row], hp[j], lp[j]);
        char* dst = A4 + (row >> 4) * 4096 + kg * 1024 + (row & 15) * 64;
#pragma unroll
        for (int j = 0; j < 4; j++)
            *(uint4*)(dst + j * 16) = make_uint4(hp[j], hp[j + 4], lp[j], lp[j + 4]);
    }

    /* per-lane top-2 for each of the 2 row-slots */
    float va0 = 3.4e38f, vb0 = 3.4e38f, va1 = 3.4e38f, vb1 = 3.4e38f;
    int   ia0 = 0, ib0 = 0, ia1 = 0, ib1 = 0;

    /* B chunk staging: 1 (n, kg16) entry per thread, gmem-coalesced */
    float4 pf[4], pfn[4];
    const int pn  = tid >> 2;         /* code index 0..63 */
    const int pkg = tid & 3;          /* kg16 0..3 */

    auto prefetch = [&](int k0, float4* r) {
        const float4* src = (const float4*)(emb + (size_t)(k0 + pn) * DDIM + pkg * 16);
        r[0] = __ldg(src);  r[1] = __ldg(src + 1);
        r[2] = __ldg(src + 2); r[3] = __ldg(src + 3);
    };
    auto sts_b = [&](const float4* r) {
        const float* v = (const float*)r;        /* 16 floats */
        uint32_t hp[8], lp[8];
#pragma unroll
        for (int j = 0; j < 8; j++)
            split2(v[2 * j], v[2 * j + 1], hp[j], lp[j]);
        char* dst = B4 + pkg * 4096 + (pn >> 3) * 512 + (pn & 7) * 64;
#pragma unroll
        for (int j = 0; j < 4; j++)
            *(uint4*)(dst + j * 16) = make_uint4(hp[j], hp[j + 4], lp[j], lp[j + 4]);
    };

    prefetch(0, pf);
    sts_b(pf);
    __syncthreads();

    const char* aw = A4 + w * 4096;

    for (int c = 0; c < NCHUNKS; c++) {
        const int k0 = c * BK;
        if (c + 1 < NCHUNKS) prefetch(k0 + BK, pfn);

        float C[8][4];
#pragma unroll
        for (int nt = 0; nt < 8; nt++)
#pragma unroll
            for (int q = 0; q < 4; q++) C[nt][q] = 0.f;

#pragma unroll
        for (int kg = 0; kg < 4; kg++) {
            uint4 f1 = *(const uint4*)(aw + kg * 1024 + g * 64 + t * 16);
            uint4 f2 = *(const uint4*)(aw + kg * 1024 + (g + 8) * 64 + t * 16);
            uint32_t ah0 = f1.x, ah1 = f2.x, ah2 = f1.y, ah3 = f2.y;
            uint32_t al0 = f1.z, al1 = f2.z, al2 = f1.w, al3 = f2.w;
            const char* bkg = B4 + kg * 4096 + g * 64 + t * 16;

#pragma unroll
            for (int nt = 0; nt < 8; nt++) {
                uint4 bv = *(const uint4*)(bkg + nt * 512);
                /* hi*hi */
                mma_bf16(C[nt][0], C[nt][1], C[nt][2], C[nt][3],
                         ah0, ah1, ah2, ah3, bv.x, bv.y);
                /* hi*lo */
                mma_bf16(C[nt][0], C[nt][1], C[nt][2], C[nt][3],
                         ah0, ah1, ah2, ah3, bv.z, bv.w);
                /* lo*hi */
                mma_bf16(C[nt][0], C[nt][1], C[nt][2], C[nt][3],
                         al0, al1, al2, al3, bv.x, bv.y);
            }
        }

        /* top-2 update: rows (w*16+g, w*16+8+g), cols k0 + nt*8 + 2t(+1) */
#pragma unroll
        for (int nt = 0; nt < 8; nt++) {
            int c0i = k0 + nt * 8 + 2 * t;
            float2 e2 = *(const float2*)(ek2s + c0i);
            float s0 = fmaf(C[nt][0], -2.f, e2.x);
            float s1 = fmaf(C[nt][1], -2.f, e2.y);
            float s2 = fmaf(C[nt][2], -2.f, e2.x);
            float s3 = fmaf(C[nt][3], -2.f, e2.y);
            if (s0 < va0)      { vb0 = va0; ib0 = ia0; va0 = s0; ia0 = c0i; }
            else if (s0 < vb0) { vb0 = s0; ib0 = c0i; }
            if (s1 < va0)      { vb0 = va0; ib0 = ia0; va0 = s1; ia0 = c0i + 1; }
            else if (s1 < vb0) { vb0 = s1; ib0 = c0i + 1; }
            if (s2 < va1)      { vb1 = va1; ib1 = ia1; va1 = s2; ia1 = c0i; }
            else if (s2 < vb1) { vb1 = s2; ib1 = c0i; }
            if (s3 < va1)      { vb1 = va1; ib1 = ia1; va1 = s3; ia1 = c0i + 1; }
            else if (s3 < vb1) { vb1 = s3; ib1 = c0i + 1; }
        }

        __syncthreads();                   /* done reading B4 chunk c */
        if (c + 1 < NCHUNKS) {
            sts_b(pfn);
            __syncthreads();               /* B4 now chunk c+1 */
        }
    }

    /* ---- cross-lane top-2 merge over t (first-occurrence tie rule on best) ---- */
#pragma unroll
    for (int o = 1; o <= 2; o <<= 1) {
        {
            float pa = __shfl_xor_sync(0xffffffffu, va0, o);
            float pb = __shfl_xor_sync(0xffffffffu, vb0, o);
            int pia = __shfl_xor_sync(0xffffffffu, ia0, o);
            int pib = __shfl_xor_sync(0xffffffffu, ib0, o);
            bool pwin = (pa < va0) || (pa == va0 && pia < ia0);
            if (pwin) {
                bool s2 = (pb < va0) || (pb == va0 && pib < ia0);
                vb0 = s2 ? pb : va0; ib0 = s2 ? pib : ia0;
                va0 = pa; ia0 = pia;
            } else {
                bool s2 = (vb0 < pa) || (vb0 == pa && ib0 < pia);
                vb0 = s2 ? vb0 : pa; ib0 = s2 ? ib0 : pia;
            }
        }
        {
            float pa = __shfl_xor_sync(0xffffffffu, va1, o);
            float pb = __shfl_xor_sync(0xffffffffu, vb1, o);
            int pia = __shfl_xor_sync(0xffffffffu, ia1, o);
            int pib = __shfl_xor_sync(0xffffffffu, ib1, o);
            bool pwin = (pa < va1) || (pa == va1 && pia < ia1);
            if (pwin) {
                bool s2 = (pb < va1) || (pb == va1 && pib < ia1);
                vb1 = s2 ? pb : va1; ib1 = s2 ? pib : ia1;
                va1 = pa; ia1 = pia;
            } else {
                bool s2 = (vb1 < pa) || (vb1 == pa && ib1 < pia);
                vb1 = s2 ? vb1 : pa; ib1 = s2 ? ib1 : pia;
            }
        }
    }

    if (t == 0) {
        int row0 = w * 16 + g, row1 = w * 16 + 8 + g;
        int bi0 = ia0;
        if (vb0 - va0 < EPS) {   /* near-tie: exact fp32 rescue */
            float da = exact_dist(zs, emb, ek2s, row0, ia0);
            float db = exact_dist(zs, emb, ek2s, row0, ib0);
            if (db < da || (db == da && ib0 < ia0)) bi0 = ib0;
        }
        int bi1 = ia1;
        if (vb1 - va1 < EPS) {
            float da = exact_dist(zs, emb, ek2s, row1, ia1);
            float db = exact_dist(zs, emb, ek2s, row1, ib1);
            if (db < da || (db == da && ib1 < ia1)) bi1 = ib1;
        }
        idx_s[row0] = bi0;
        idx_s[row1] = bi1;
    }
    __syncthreads();

    /* ---- epilogue: gather codebook rows, transposed coalesced store, loss ---- */
    float* outb = out + (size_t)b * DDIM * HW + hw0;
    float lsum = 0.f;
#pragma unroll
    for (int it = 0; it < 32; it++) {
        int e = it * NTHREADS + tid;       /* 8192 elements */
        int d = e >> 7, i = e & 127;
        float q = __ldg(emb + (size_t)idx_s[i] * DDIM + d);
        outb[(size_t)d * HW + i] = q;
        float diff = q - zs[d * MROWS + i];
        lsum += diff * diff;
    }
#pragma unroll
    for (int o = 16; o > 0; o >>= 1)
        lsum += __shfl_xor_sync(0xffffffffu, lsum, o);
    if (lane == 0) wsum[w] = lsum;
    __syncthreads();
    if (tid == 0) {
        float tot = 0.f;
#pragma unroll
        for (int j = 0; j < 8; j++) tot += wsum[j];
        atomicAdd(&g_loss, (double)tot);
    }
}

/* ================= launch ================= */
extern "C" void kernel_launch(void* const* d_in, const int* in_sizes, int n_in,
                              void* d_out, int out_size) {
    const float* z   = (const float*)d_in[0];
    const float* emb = (const float*)d_in[1];
    float* out = (float*)d_out;

    static int attr_set = 0;
    if (!attr_set) {
        cudaFuncSetAttribute(vq_kernel, cudaFuncAttributeMaxDynamicSharedMemorySize,
                             SMEM_TOTAL);
        attr_set = 1;
    }

    zero_loss_kernel<<<1, 1>>>();
    ek2_kernel<<<KCODES / 128, 128>>>(emb);
    vq_kernel<<<NTOT / MROWS, NTHREADS, SMEM_TOTAL>>>(z, emb, out);
    finalize_kernel<<<1, 1>>>(out, out_size - 1);
}